// round 1
// baseline (speedup 1.0000x reference)
#include <cuda_runtime.h>
#include <cstdint>

// Problem constants (fixed by the reference)
#define N_NODES   100000
#define N_EDGES   1600000
#define IN_FEATS  64
#define OUT_FEATS 32

// Scratch (no cudaMalloc allowed)
__device__ float g_hW[N_NODES * OUT_FEATS];   // 12.8 MB
__device__ float g_deg[N_NODES];              // 0.4 MB

// ---------------------------------------------------------------------------
// Kernel 1: zero the accumulator (d_out) and degree buffer
// ---------------------------------------------------------------------------
__global__ void zero_kernel(float* __restrict__ out, int n_out) {
    int stride = gridDim.x * blockDim.x;
    for (int i = blockIdx.x * blockDim.x + threadIdx.x; i < n_out; i += stride)
        out[i] = 0.0f;
    for (int i = blockIdx.x * blockDim.x + threadIdx.x; i < N_NODES; i += stride)
        g_deg[i] = 0.0f;
}

// ---------------------------------------------------------------------------
// Kernel 2: hW = h @ W     [N,64] x [64,32] -> [N,32]
// One thread per node row; W staged in shared memory (8 KB).
// ---------------------------------------------------------------------------
__global__ void gemm_kernel(const float* __restrict__ h,
                            const float* __restrict__ W) {
    __shared__ float sW[IN_FEATS * OUT_FEATS];  // 2048 floats
    for (int i = threadIdx.x; i < IN_FEATS * OUT_FEATS; i += blockDim.x)
        sW[i] = W[i];
    __syncthreads();

    int node = blockIdx.x * blockDim.x + threadIdx.x;
    if (node >= N_NODES) return;

    const float4* hrow = reinterpret_cast<const float4*>(h + (size_t)node * IN_FEATS);

    float acc[OUT_FEATS];
    #pragma unroll
    for (int j = 0; j < OUT_FEATS; j++) acc[j] = 0.0f;

    #pragma unroll
    for (int k4 = 0; k4 < IN_FEATS / 4; k4++) {
        float4 hv = hrow[k4];
        const float* w0 = &sW[(k4 * 4 + 0) * OUT_FEATS];
        const float* w1 = &sW[(k4 * 4 + 1) * OUT_FEATS];
        const float* w2 = &sW[(k4 * 4 + 2) * OUT_FEATS];
        const float* w3 = &sW[(k4 * 4 + 3) * OUT_FEATS];
        #pragma unroll
        for (int j = 0; j < OUT_FEATS; j++) {
            acc[j] += hv.x * w0[j];
            acc[j] += hv.y * w1[j];
            acc[j] += hv.z * w2[j];
            acc[j] += hv.w * w3[j];
        }
    }

    float4* orow = reinterpret_cast<float4*>(g_hW + (size_t)node * OUT_FEATS);
    #pragma unroll
    for (int j4 = 0; j4 < OUT_FEATS / 4; j4++) {
        float4 v;
        v.x = acc[j4 * 4 + 0];
        v.y = acc[j4 * 4 + 1];
        v.z = acc[j4 * 4 + 2];
        v.w = acc[j4 * 4 + 3];
        orow[j4] = v;
    }
}

// ---------------------------------------------------------------------------
// Kernel 3: edge scatter. 8 threads per edge, each handles 4 contiguous
// feature floats via a single vectorized red.global.add.v4.f32.
// Also accumulates the degree (one lane per edge).
// ---------------------------------------------------------------------------
__global__ void scatter_kernel(const int*   __restrict__ src,
                               const int*   __restrict__ dst,
                               const float* __restrict__ order,
                               float*       __restrict__ agg) {
    int t   = blockIdx.x * blockDim.x + threadIdx.x;
    int e   = t >> 3;        // edge index
    int sub = t & 7;         // which 4-float chunk of the 32 features
    if (e >= N_EDGES) return;

    int   s = src[e];
    int   d = dst[e];
    float w = order[e];

    float4 v = *reinterpret_cast<const float4*>(g_hW + (size_t)s * OUT_FEATS + sub * 4);
    v.x *= w; v.y *= w; v.z *= w; v.w *= w;

    float* a = agg + (size_t)d * OUT_FEATS + sub * 4;
    asm volatile("red.global.add.v4.f32 [%0], {%1, %2, %3, %4};"
                 :: "l"(a), "f"(v.x), "f"(v.y), "f"(v.z), "f"(v.w)
                 : "memory");

    if (sub == 0)
        atomicAdd(g_deg + d, 1.0f);
}

// ---------------------------------------------------------------------------
// Kernel 4: out = relu(agg / max(deg,1) + b), in place on d_out
// One thread per output element.
// ---------------------------------------------------------------------------
__global__ void finalize_kernel(float* __restrict__ out,
                                const float* __restrict__ b) {
    __shared__ float sb[OUT_FEATS];
    if (threadIdx.x < OUT_FEATS) sb[threadIdx.x] = b[threadIdx.x];
    __syncthreads();

    int t = blockIdx.x * blockDim.x + threadIdx.x;
    if (t >= N_NODES * OUT_FEATS) return;
    int n = t >> 5;   // node
    int j = t & 31;   // feature

    float deg  = g_deg[n];
    float norm = 1.0f / fmaxf(deg, 1.0f);
    float v    = out[t] * norm + sb[j];
    out[t] = fmaxf(v, 0.0f);
}

// ---------------------------------------------------------------------------
// Launch
// ---------------------------------------------------------------------------
extern "C" void kernel_launch(void* const* d_in, const int* in_sizes, int n_in,
                              void* d_out, int out_size) {
    const float* h     = (const float*)d_in[0];   // [N, 64]
    const int*   src   = (const int*)  d_in[1];   // [E]
    const int*   dst   = (const int*)  d_in[2];   // [E]
    const float* order = (const float*)d_in[3];   // [E]
    const float* W     = (const float*)d_in[4];   // [64, 32]
    const float* b     = (const float*)d_in[5];   // [32]
    float*       out   = (float*)d_out;           // [N, 32]

    (void)in_sizes; (void)n_in; (void)out_size;

    // 1) zero accumulators (d_out used directly as agg buffer)
    zero_kernel<<<1024, 256>>>(out, N_NODES * OUT_FEATS);

    // 2) hW = h @ W
    gemm_kernel<<<(N_NODES + 255) / 256, 256>>>(h, W);

    // 3) edge scatter (atomic accumulate into d_out + degree count)
    {
        long long total = (long long)N_EDGES * 8;
        int blocks = (int)((total + 255) / 256);
        scatter_kernel<<<blocks, 256>>>(src, dst, order, out);
    }

    // 4) normalize + bias + relu, in place
    finalize_kernel<<<(N_NODES * OUT_FEATS + 255) / 256, 256>>>(out, b);
}

// round 2
// speedup vs baseline: 1.0961x; 1.0961x over previous
#include <cuda_runtime.h>
#include <cstdint>

#define N_NODES   100000
#define N_EDGES   1600000
#define IN_FEATS  64
#define OUT_FEATS 32

// Scratch (no cudaMalloc allowed)
__device__ float g_hW[N_NODES * OUT_FEATS];   // 12.8 MB
__device__ float g_deg[N_NODES];              // 0.4 MB

// ---------------------------------------------------------------------------
// Kernel 1: fused  (a) zero d_out + g_deg,  (b) hW = h @ W
// One thread per node row. W staged in shared as float4 -> LDS.128 inner loop.
// ---------------------------------------------------------------------------
__global__ void __launch_bounds__(256) gemm_zero_kernel(
        const float* __restrict__ h,
        const float* __restrict__ W,
        float*       __restrict__ out) {
    __shared__ float4 sW4[IN_FEATS * OUT_FEATS / 4];   // 512 float4 = 8KB

    // stage W (vectorized)
    {
        const float4* W4 = reinterpret_cast<const float4*>(W);
        for (int i = threadIdx.x; i < IN_FEATS * OUT_FEATS / 4; i += blockDim.x)
            sW4[i] = W4[i];
    }

    // grid-stride zero of out (800000 float4) and g_deg (100000 floats)
    {
        int tg     = blockIdx.x * blockDim.x + threadIdx.x;
        int stride = gridDim.x * blockDim.x;
        float4 z = make_float4(0.f, 0.f, 0.f, 0.f);
        float4* out4 = reinterpret_cast<float4*>(out);
        for (int i = tg; i < N_NODES * OUT_FEATS / 4; i += stride)
            out4[i] = z;
        for (int i = tg; i < N_NODES; i += stride)
            g_deg[i] = 0.0f;
    }
    __syncthreads();

    int node = blockIdx.x * blockDim.x + threadIdx.x;
    if (node >= N_NODES) return;

    const float4* hrow = reinterpret_cast<const float4*>(h + (size_t)node * IN_FEATS);

    float acc[OUT_FEATS];
    #pragma unroll
    for (int j = 0; j < OUT_FEATS; j++) acc[j] = 0.0f;

    #pragma unroll
    for (int k4 = 0; k4 < IN_FEATS / 4; k4++) {
        float4 hv = hrow[k4];
        #pragma unroll
        for (int kk = 0; kk < 4; kk++) {
            float hk = (kk == 0) ? hv.x : (kk == 1) ? hv.y : (kk == 2) ? hv.z : hv.w;
            const float4* wr = &sW4[(k4 * 4 + kk) * (OUT_FEATS / 4)];
            #pragma unroll
            for (int j4 = 0; j4 < OUT_FEATS / 4; j4++) {
                float4 w = wr[j4];
                acc[j4 * 4 + 0] = fmaf(hk, w.x, acc[j4 * 4 + 0]);
                acc[j4 * 4 + 1] = fmaf(hk, w.y, acc[j4 * 4 + 1]);
                acc[j4 * 4 + 2] = fmaf(hk, w.z, acc[j4 * 4 + 2]);
                acc[j4 * 4 + 3] = fmaf(hk, w.w, acc[j4 * 4 + 3]);
            }
        }
    }

    float4* orow = reinterpret_cast<float4*>(g_hW + (size_t)node * OUT_FEATS);
    #pragma unroll
    for (int j4 = 0; j4 < OUT_FEATS / 4; j4++)
        orow[j4] = make_float4(acc[j4 * 4 + 0], acc[j4 * 4 + 1],
                               acc[j4 * 4 + 2], acc[j4 * 4 + 3]);
}

// ---------------------------------------------------------------------------
// Kernel 2: edge scatter. 8 threads per edge, one red.global.add.v4.f32 each.
// ---------------------------------------------------------------------------
__global__ void __launch_bounds__(256) scatter_kernel(
        const int*   __restrict__ src,
        const int*   __restrict__ dst,
        const float* __restrict__ order,
        float*       __restrict__ agg) {
    int t   = blockIdx.x * blockDim.x + threadIdx.x;
    int e   = t >> 3;
    int sub = t & 7;
    if (e >= N_EDGES) return;

    int   s = __ldg(src + e);
    int   d = __ldg(dst + e);
    float w = __ldg(order + e);

    float4 v = __ldg(reinterpret_cast<const float4*>(
                         g_hW + (size_t)s * OUT_FEATS + sub * 4));
    v.x *= w; v.y *= w; v.z *= w; v.w *= w;

    float* a = agg + (size_t)d * OUT_FEATS + sub * 4;
    asm volatile("red.global.add.v4.f32 [%0], {%1, %2, %3, %4};"
                 :: "l"(a), "f"(v.x), "f"(v.y), "f"(v.z), "f"(v.w)
                 : "memory");

    if (sub == 0)
        atomicAdd(g_deg + d, 1.0f);
}

// ---------------------------------------------------------------------------
// Kernel 3: out = relu(agg/max(deg,1) + b), in place, float4-vectorized.
// One thread per float4 (8 threads per node row).
// ---------------------------------------------------------------------------
__global__ void __launch_bounds__(256) finalize_kernel(
        float* __restrict__ out,
        const float* __restrict__ b) {
    int t = blockIdx.x * blockDim.x + threadIdx.x;   // float4 index
    if (t >= N_NODES * OUT_FEATS / 4) return;
    int n  = t >> 3;   // node
    int j4 = t & 7;    // float4 within row

    float  deg  = __ldg(g_deg + n);
    float  norm = 1.0f / fmaxf(deg, 1.0f);
    float4 bb   = __ldg(reinterpret_cast<const float4*>(b) + j4);

    float4* out4 = reinterpret_cast<float4*>(out);
    float4 v = out4[t];
    v.x = fmaxf(fmaf(v.x, norm, bb.x), 0.0f);
    v.y = fmaxf(fmaf(v.y, norm, bb.y), 0.0f);
    v.z = fmaxf(fmaf(v.z, norm, bb.z), 0.0f);
    v.w = fmaxf(fmaf(v.w, norm, bb.w), 0.0f);
    out4[t] = v;
}

// ---------------------------------------------------------------------------
// Launch
// ---------------------------------------------------------------------------
extern "C" void kernel_launch(void* const* d_in, const int* in_sizes, int n_in,
                              void* d_out, int out_size) {
    const float* h     = (const float*)d_in[0];
    const int*   src   = (const int*)  d_in[1];
    const int*   dst   = (const int*)  d_in[2];
    const float* order = (const float*)d_in[3];
    const float* W     = (const float*)d_in[4];
    const float* b     = (const float*)d_in[5];
    float*       out   = (float*)d_out;

    (void)in_sizes; (void)n_in; (void)out_size;

    gemm_zero_kernel<<<(N_NODES + 255) / 256, 256>>>(h, W, out);

    {
        long long total = (long long)N_EDGES * 8;
        int blocks = (int)((total + 255) / 256);
        scatter_kernel<<<blocks, 256>>>(src, dst, order, out);
    }

    finalize_kernel<<<(N_NODES * OUT_FEATS / 4 + 255) / 256, 256>>>(out, b);
}